// round 7
// baseline (speedup 1.0000x reference)
#include <cuda_runtime.h>

#define L_CHK 64                 // chunk length along T
#define SCRATCH_CAP (1 << 21)    // 2M float2 = 16 MB each

__device__ float2 g_carry [SCRATCH_CAP];
__device__ float2 g_prefix[SCRATCH_CAP];

// ---------------------------------------------------------------------------
// Pass 1: per-chunk local scan from v=0; store end-of-chunk carry.
// ---------------------------------------------------------------------------
__global__ void __launch_bounds__(256) dln_pass1(
    const float* __restrict__ x,
    const float* __restrict__ sz,
    const float* __restrict__ th,
    int D, int T, int C)
{
    const int d = blockIdx.x * blockDim.x + threadIdx.x;
    const int c = blockIdx.y;
    if (d >= D || c >= C) return;

    const int t0  = c * L_CHK;
    const int len = (T - t0 < L_CHK) ? (T - t0) : L_CHK;

    const float r = expf(-expf(sz[d]));
    float si, co;
    sincosf(th[d], &si, &co);
    const float zr = r * co, zi = r * si;

    const float* xp = x + (long long)t0 * D + d;

    float vr = 0.f, vi = 0.f;
    for (int t = 0; t < len; ++t) {
        const float xv = xp[(long long)t * D];
        const float nvr = fmaf(zr, vr, fmaf(-zi, vi, xv));
        const float nvi = fmaf(zi, vr, zr * vi);
        vr = nvr; vi = nvi;
    }
    g_carry[(long long)c * D + d] = make_float2(vr, vi);
}

// ---------------------------------------------------------------------------
// Pass 2: per-channel exclusive scan over chunk carries, multiplier z^L.
// ---------------------------------------------------------------------------
__global__ void __launch_bounds__(256) dln_pass2(
    const float* __restrict__ sz,
    const float* __restrict__ th,
    int D, int C)
{
    const int d = blockIdx.x * blockDim.x + threadIdx.x;
    if (d >= D) return;

    const float rL = expf(-(float)L_CHK * expf(sz[d]));  // underflow->0 ok
    float si, co;
    sincosf((float)L_CHK * th[d], &si, &co);
    const float zLr = rL * co, zLi = rL * si;

    float vr = 0.f, vi = 0.f;
    for (int c = 0; c < C; ++c) {
        const long long idx = (long long)c * D + d;
        g_prefix[idx] = make_float2(vr, vi);
        const float2 cv = g_carry[idx];
        const float nvr = fmaf(zLr, vr, fmaf(-zLi, vi, cv.x));
        const float nvi = fmaf(zLi, vr, fmaf(zLr, vi, cv.y));
        vr = nvr; vi = nvi;
    }
}

// ---------------------------------------------------------------------------
// Pass 3: replay each chunk seeded with its prefix.
// interleaved == 0: write REAL part only to out[t*D + d]        (f32 [T,D])
// interleaved == 1: write (re,im) floats at out[2*(t*D+d) + {0,1}]
// Every store is scalar f32 and bounded by out_cap_floats.
// ---------------------------------------------------------------------------
__global__ void __launch_bounds__(256) dln_pass3(
    const float* __restrict__ x,
    const float* __restrict__ sz,
    const float* __restrict__ th,
    float* __restrict__ out,
    int D, int T, int C, int interleaved, long long out_cap_floats)
{
    const int d = blockIdx.x * blockDim.x + threadIdx.x;
    const int c = blockIdx.y;
    if (d >= D || c >= C) return;

    const int t0  = c * L_CHK;
    const int len = (T - t0 < L_CHK) ? (T - t0) : L_CHK;

    const float r = expf(-expf(sz[d]));
    float si, co;
    sincosf(th[d], &si, &co);
    const float zr = r * co, zi = r * si;

    const float2 v0 = g_prefix[(long long)c * D + d];
    float vr = v0.x, vi = v0.y;

    const float* xp = x + (long long)t0 * D + d;

    for (int t = 0; t < len; ++t) {
        const float xv = xp[(long long)t * D];
        const float nvr = fmaf(zr, vr, fmaf(-zi, vi, xv));
        const float nvi = fmaf(zi, vr, zr * vi);
        vr = nvr; vi = nvi;

        const long long lidx = (long long)(t0 + t) * D + d;
        if (interleaved) {
            const long long o = 2 * lidx;
            if (o + 1 < out_cap_floats) { out[o] = vr; out[o + 1] = vi; }
        } else {
            if (lidx < out_cap_floats) out[lidx] = vr;
        }
    }
}

extern "C" void kernel_launch(void* const* d_in, const int* in_sizes, int n_in,
                              void* d_out, int out_size)
{
    if (n_in < 3) return;

    // x = largest input; remaining two in original order = (size, theta).
    int xi = 0;
    for (int i = 1; i < n_in; ++i)
        if (in_sizes[i] > in_sizes[xi]) xi = i;

    const float* x = (const float*)d_in[xi];
    const float* sv[2] = {nullptr, nullptr};
    long long    ss[2] = {0, 0};
    int ns = 0;
    for (int i = 0; i < n_in && ns < 2; ++i)
        if (i != xi) { sv[ns] = (const float*)d_in[i]; ss[ns] = in_sizes[i]; ++ns; }
    if (ns < 2) return;
    const float* sz = sv[0];
    const float* th = sv[1];

    const long long big   = in_sizes[xi];
    const long long small = ss[0] < ss[1] ? ss[0] : ss[1];
    if (small <= 0 || big <= 0 || big % small) return;

    // T = big/small is unit-invariant (elements or bytes scale both equally).
    const long long T = big / small;
    if (T <= 0 || T > (1 << 20)) return;

    // Derive D and output mode from out_size (documented: ELEMENT count).
    const long long osz = out_size;
    long long D = 0;
    int interleaved = 0;
    if (osz % T == 0 && (osz / T == small || 4 * (osz / T) == small)) {
        D = osz / T;            // out = T*D f32 (real part)
        interleaved = 0;
    } else if (osz % (2 * T) == 0 &&
               (osz / (2 * T) == small || 4 * (osz / (2 * T)) == small)) {
        D = osz / (2 * T);      // out = 2*T*D f32 (interleaved complex)
        interleaved = 1;
    } else {
        return;                 // unrecognized geometry -> distinguishable error
    }
    if (D <= 0 || D > (1 << 20)) return;

    const int C = (int)((T + L_CHK - 1) / L_CHK);
    if ((long long)C * D > (long long)SCRATCH_CAP) return;

    dim3 blk(256);
    dim3 gridA((unsigned)((D + 255) / 256), (unsigned)C);
    dln_pass1<<<gridA, blk>>>(x, sz, th, (int)D, (int)T, C);
    dln_pass2<<<(unsigned)((D + 255) / 256), blk>>>(sz, th, (int)D, C);
    dln_pass3<<<gridA, blk>>>(x, sz, th, (float*)d_out,
                              (int)D, (int)T, C, interleaved, osz);
}

// round 9
// speedup vs baseline: 1.1307x; 1.1307x over previous
#include <cuda_runtime.h>

#define L_CHK 64                 // chunk length along T
#define SCRATCH_CAP (1 << 21)    // 2M float2 = 16 MB each

__device__ float2 g_carry [SCRATCH_CAP];
__device__ float2 g_prefix[SCRATCH_CAP];

// ---------------------------------------------------------------------------
// Pass 1: per-chunk local scan from v=0; store end-of-chunk carry.
// Fast path: full chunk, fully unrolled -> deep MLP on the x loads.
// ---------------------------------------------------------------------------
__global__ void __launch_bounds__(256) dln_pass1(
    const float* __restrict__ x,
    const float* __restrict__ sz,
    const float* __restrict__ th,
    int D, int T, int C)
{
    const int d = blockIdx.x * blockDim.x + threadIdx.x;
    const int c = blockIdx.y;
    if (d >= D || c >= C) return;

    const int t0  = c * L_CHK;
    const int len = (T - t0 < L_CHK) ? (T - t0) : L_CHK;

    const float r = expf(-expf(sz[d]));
    float si, co;
    sincosf(th[d], &si, &co);
    const float zr = r * co, zi = r * si;

    const float* xp = x + (long long)t0 * D + d;

    float vr = 0.f, vi = 0.f;
    if (len == L_CHK) {
#pragma unroll
        for (int t = 0; t < L_CHK; ++t) {
            const float xv = xp[(long long)t * D];
            const float nvr = fmaf(zr, vr, fmaf(-zi, vi, xv));
            const float nvi = fmaf(zi, vr, zr * vi);
            vr = nvr; vi = nvi;
        }
    } else {
        for (int t = 0; t < len; ++t) {
            const float xv = xp[(long long)t * D];
            const float nvr = fmaf(zr, vr, fmaf(-zi, vi, xv));
            const float nvi = fmaf(zi, vr, zr * vi);
            vr = nvr; vi = nvi;
        }
    }
    g_carry[(long long)c * D + d] = make_float2(vr, vi);
}

// ---------------------------------------------------------------------------
// Pass 2: per-channel exclusive scan over chunk carries, multiplier z^L.
// ---------------------------------------------------------------------------
__global__ void __launch_bounds__(256) dln_pass2(
    const float* __restrict__ sz,
    const float* __restrict__ th,
    int D, int C)
{
    const int d = blockIdx.x * blockDim.x + threadIdx.x;
    if (d >= D) return;

    const float rL = expf(-(float)L_CHK * expf(sz[d]));  // underflow->0 ok
    float si, co;
    sincosf((float)L_CHK * th[d], &si, &co);
    const float zLr = rL * co, zLi = rL * si;

    float vr = 0.f, vi = 0.f;
    for (int c = 0; c < C; ++c) {
        const long long idx = (long long)c * D + d;
        g_prefix[idx] = make_float2(vr, vi);
        const float2 cv = g_carry[idx];
        const float nvr = fmaf(zLr, vr, fmaf(-zLi, vi, cv.x));
        const float nvi = fmaf(zLi, vr, fmaf(zLr, vi, cv.y));
        vr = nvr; vi = nvi;
    }
}

// ---------------------------------------------------------------------------
// Pass 3a (REAL mode): replay chunk, store real part only, streaming stores.
// ---------------------------------------------------------------------------
__global__ void __launch_bounds__(256) dln_pass3_real(
    const float* __restrict__ x,
    const float* __restrict__ sz,
    const float* __restrict__ th,
    float* __restrict__ out,
    int D, int T, int C, long long out_cap_floats)
{
    const int d = blockIdx.x * blockDim.x + threadIdx.x;
    const int c = blockIdx.y;
    if (d >= D || c >= C) return;

    const int t0  = c * L_CHK;
    const int len = (T - t0 < L_CHK) ? (T - t0) : L_CHK;

    const float r = expf(-expf(sz[d]));
    float si, co;
    sincosf(th[d], &si, &co);
    const float zr = r * co, zi = r * si;

    const float2 v0 = g_prefix[(long long)c * D + d];
    float vr = v0.x, vi = v0.y;

    const float* xp = x + (long long)t0 * D + d;

    if (len == L_CHK && (long long)(t0 + L_CHK) * D <= out_cap_floats) {
        float* op = out + (long long)t0 * D + d;
#pragma unroll
        for (int t = 0; t < L_CHK; ++t) {
            const float xv = xp[(long long)t * D];
            const float nvr = fmaf(zr, vr, fmaf(-zi, vi, xv));
            const float nvi = fmaf(zi, vr, zr * vi);
            vr = nvr; vi = nvi;
            __stcs(op + (long long)t * D, vr);
        }
    } else {
        for (int t = 0; t < len; ++t) {
            const float xv = xp[(long long)t * D];
            const float nvr = fmaf(zr, vr, fmaf(-zi, vi, xv));
            const float nvi = fmaf(zi, vr, zr * vi);
            vr = nvr; vi = nvi;
            const long long lidx = (long long)(t0 + t) * D + d;
            if (lidx < out_cap_floats) __stcs(out + lidx, vr);
        }
    }
}

// ---------------------------------------------------------------------------
// Pass 3b (INTERLEAVED mode): store (re, im) as two scalar f32, streaming.
// ---------------------------------------------------------------------------
__global__ void __launch_bounds__(256) dln_pass3_cplx(
    const float* __restrict__ x,
    const float* __restrict__ sz,
    const float* __restrict__ th,
    float* __restrict__ out,
    int D, int T, int C, long long out_cap_floats)
{
    const int d = blockIdx.x * blockDim.x + threadIdx.x;
    const int c = blockIdx.y;
    if (d >= D || c >= C) return;

    const int t0  = c * L_CHK;
    const int len = (T - t0 < L_CHK) ? (T - t0) : L_CHK;

    const float r = expf(-expf(sz[d]));
    float si, co;
    sincosf(th[d], &si, &co);
    const float zr = r * co, zi = r * si;

    const float2 v0 = g_prefix[(long long)c * D + d];
    float vr = v0.x, vi = v0.y;

    const float* xp = x + (long long)t0 * D + d;

    if (len == L_CHK && 2 * (long long)(t0 + L_CHK) * D <= out_cap_floats) {
        float* op = out + 2 * ((long long)t0 * D + d);
#pragma unroll
        for (int t = 0; t < L_CHK; ++t) {
            const float xv = xp[(long long)t * D];
            const float nvr = fmaf(zr, vr, fmaf(-zi, vi, xv));
            const float nvi = fmaf(zi, vr, zr * vi);
            vr = nvr; vi = nvi;
            __stcs(op + 2 * (long long)t * D,     vr);
            __stcs(op + 2 * (long long)t * D + 1, vi);
        }
    } else {
        for (int t = 0; t < len; ++t) {
            const float xv = xp[(long long)t * D];
            const float nvr = fmaf(zr, vr, fmaf(-zi, vi, xv));
            const float nvi = fmaf(zi, vr, zr * vi);
            vr = nvr; vi = nvi;
            const long long o = 2 * ((long long)(t0 + t) * D + d);
            if (o + 1 < out_cap_floats) {
                __stcs(out + o,     vr);
                __stcs(out + o + 1, vi);
            }
        }
    }
}

extern "C" void kernel_launch(void* const* d_in, const int* in_sizes, int n_in,
                              void* d_out, int out_size)
{
    if (n_in < 3) return;

    // x = largest input; remaining two in original order = (size, theta).
    int xi = 0;
    for (int i = 1; i < n_in; ++i)
        if (in_sizes[i] > in_sizes[xi]) xi = i;

    const float* x = (const float*)d_in[xi];
    const float* sv[2] = {nullptr, nullptr};
    long long    ss[2] = {0, 0};
    int ns = 0;
    for (int i = 0; i < n_in && ns < 2; ++i)
        if (i != xi) { sv[ns] = (const float*)d_in[i]; ss[ns] = in_sizes[i]; ++ns; }
    if (ns < 2) return;
    const float* sz = sv[0];
    const float* th = sv[1];

    const long long big   = in_sizes[xi];
    const long long small = ss[0] < ss[1] ? ss[0] : ss[1];
    if (small <= 0 || big <= 0 || big % small) return;

    // T = big/small is unit-invariant.
    const long long T = big / small;
    if (T <= 0 || T > (1 << 20)) return;

    // Derive D and output mode from out_size (element count).
    const long long osz = out_size;
    long long D = 0;
    int interleaved = 0;
    if (osz % T == 0 && (osz / T == small || 4 * (osz / T) == small)) {
        D = osz / T;            // out = T*D f32 (real part)
        interleaved = 0;
    } else if (osz % (2 * T) == 0 &&
               (osz / (2 * T) == small || 4 * (osz / (2 * T)) == small)) {
        D = osz / (2 * T);      // out = 2*T*D f32 (interleaved complex)
        interleaved = 1;
    } else {
        return;
    }
    if (D <= 0 || D > (1 << 20)) return;

    const int C = (int)((T + L_CHK - 1) / L_CHK);
    if ((long long)C * D > (long long)SCRATCH_CAP) return;

    dim3 blk(256);
    dim3 gridA((unsigned)((D + 255) / 256), (unsigned)C);
    dln_pass1<<<gridA, blk>>>(x, sz, th, (int)D, (int)T, C);
    dln_pass2<<<(unsigned)((D + 255) / 256), blk>>>(sz, th, (int)D, C);
    if (interleaved)
        dln_pass3_cplx<<<gridA, blk>>>(x, sz, th, (float*)d_out,
                                       (int)D, (int)T, C, osz);
    else
        dln_pass3_real<<<gridA, blk>>>(x, sz, th, (float*)d_out,
                                       (int)D, (int)T, C, osz);
}